// round 1
// baseline (speedup 1.0000x reference)
#include <cuda_runtime.h>
#include <math.h>

#define NTOK 16384
#define DM   1024
#define NE   4
#define DH   2048   // 2*d

// ---------------- scratch (static device globals; no runtime allocation) ----
__device__ int   g_count[NE];
__device__ int   g_tok [NE * NTOK];       // expert -> list of token ids (slot order)
__device__ int   g_eid [NTOK * 2];        // per token: its 2 expert ids
__device__ int   g_slot[NTOK * 2];        // per token: slot within each expert list
__device__ float g_wt  [NTOK * 2];        // per token: softmax weights
__device__ float g_H[(size_t)NE * NTOK * DH];   // 512 MB: gelu(x@W1^T+b1), slot order
__device__ float g_Z[(size_t)NE * NTOK * DM];   // 256 MB: H@W2^T+b2, slot order

// ---------------- reset (graph replays must re-zero the counters) -----------
__global__ void reset_kernel() {
    if (threadIdx.x < NE) g_count[threadIdx.x] = 0;
}

// ---------------- gating: scores, top-2 softmax, routing lists --------------
__global__ void gate_kernel(const float* __restrict__ x,
                            const float* __restrict__ gw) {
    int t    = blockIdx.x;
    int tid  = threadIdx.x;          // 128 threads: warp w computes score of expert w
    int w    = tid >> 5;
    int lane = tid & 31;

    const float4* xr = (const float4*)(x + (size_t)t * DM);
    const float4* gr = (const float4*)(gw + (size_t)w * DM);
    float s = 0.f;
    #pragma unroll
    for (int k = lane; k < DM / 4; k += 32) {
        float4 a = xr[k], b = gr[k];
        s += a.x * b.x + a.y * b.y + a.z * b.z + a.w * b.w;
    }
    #pragma unroll
    for (int o = 16; o; o >>= 1) s += __shfl_xor_sync(0xffffffffu, s, o);

    __shared__ float sc[NE];
    if (lane == 0) sc[w] = s;
    __syncthreads();

    if (tid == 0) {
        // top-2 with jax top_k tie-break (lowest index wins on ties)
        int i0 = 0;
        #pragma unroll
        for (int i = 1; i < NE; i++) if (sc[i] > sc[i0]) i0 = i;
        int i1 = -1;
        #pragma unroll
        for (int i = 0; i < NE; i++) {
            if (i == i0) continue;
            if (i1 < 0 || sc[i] > sc[i1]) i1 = i;
        }
        float m  = fmaxf(sc[i0], sc[i1]);
        float e0 = expf(sc[i0] - m), e1 = expf(sc[i1] - m);
        float inv = 1.f / (e0 + e1);

        int s0 = atomicAdd(&g_count[i0], 1);
        int s1 = atomicAdd(&g_count[i1], 1);
        g_eid [t * 2]     = i0;  g_eid [t * 2 + 1] = i1;
        g_slot[t * 2]     = s0;  g_slot[t * 2 + 1] = s1;
        g_wt  [t * 2]     = e0 * inv;
        g_wt  [t * 2 + 1] = e1 * inv;
        g_tok[i0 * NTOK + s0] = t;
        g_tok[i1 * NTOK + s1] = t;
    }
}

// ---------------- tiled SGEMM (NT layout: C[m,n] = sum_k A[m,k]*B[n,k]) -----
// PHASE 1: A = gathered x rows   [cnt,1024],  B = w1[e] [2048,1024], out = gelu(.)+b1 -> g_H
// PHASE 2: A = g_H rows (slots)  [cnt,2048],  B = w2[e] [1024,2048], out = . + b2    -> g_Z
template <int PHASE>
__global__ void __launch_bounds__(256, 2)
gemm_kernel(const float* __restrict__ Ain,
            const float* __restrict__ W,
            const float* __restrict__ bias) {
    constexpr int K  = (PHASE == 1) ? DM : DH;
    constexpr int N  = (PHASE == 1) ? DH : DM;
    constexpr int BM = 128, BN = 128, BK = 16, TM = 8, TN = 8;

    __shared__ float As[BK][BM];
    __shared__ float Bs[BK][BN];

    const int e   = blockIdx.z;
    const int cnt = g_count[e];
    const int m0  = blockIdx.y * BM;
    if (m0 >= cnt) return;
    const int n0  = blockIdx.x * BN;

    const int tid = threadIdx.x;        // 256
    const int tx  = tid & 15;           // 16 cols of threads
    const int ty  = tid >> 4;           // 16 rows of threads

    const float* A  = (PHASE == 1) ? Ain : (g_H + (size_t)e * NTOK * DH);
    const float* Bw = W + (size_t)e * N * K;

    // load mapping: thread loads rows (tid/4, tid/4+64), 4 consecutive k's at kq
    const int lrow = tid >> 2;
    const int lkq  = (tid & 3) * 4;

    size_t arow0, arow1;
    {
        int r0 = m0 + lrow, r1 = m0 + lrow + 64;
        if (PHASE == 1) {
            int t0 = (r0 < cnt) ? g_tok[e * NTOK + r0] : 0;
            int t1 = (r1 < cnt) ? g_tok[e * NTOK + r1] : 0;
            arow0 = (size_t)t0 * K;
            arow1 = (size_t)t1 * K;
        } else {
            arow0 = (size_t)r0 * K;     // in-bounds; garbage rows never stored
            arow1 = (size_t)r1 * K;
        }
    }
    const size_t brow0 = (size_t)(n0 + lrow) * K;
    const size_t brow1 = (size_t)(n0 + lrow + 64) * K;

    float acc[TM][TN];
    #pragma unroll
    for (int i = 0; i < TM; i++)
        #pragma unroll
        for (int j = 0; j < TN; j++) acc[i][j] = 0.f;

    for (int kb = 0; kb < K; kb += BK) {
        float4 a0 = *(const float4*)(A  + arow0 + kb + lkq);
        float4 a1 = *(const float4*)(A  + arow1 + kb + lkq);
        float4 b0 = *(const float4*)(Bw + brow0 + kb + lkq);
        float4 b1 = *(const float4*)(Bw + brow1 + kb + lkq);

        As[lkq + 0][lrow]      = a0.x; As[lkq + 1][lrow]      = a0.y;
        As[lkq + 2][lrow]      = a0.z; As[lkq + 3][lrow]      = a0.w;
        As[lkq + 0][lrow + 64] = a1.x; As[lkq + 1][lrow + 64] = a1.y;
        As[lkq + 2][lrow + 64] = a1.z; As[lkq + 3][lrow + 64] = a1.w;
        Bs[lkq + 0][lrow]      = b0.x; Bs[lkq + 1][lrow]      = b0.y;
        Bs[lkq + 2][lrow]      = b0.z; Bs[lkq + 3][lrow]      = b0.w;
        Bs[lkq + 0][lrow + 64] = b1.x; Bs[lkq + 1][lrow + 64] = b1.y;
        Bs[lkq + 2][lrow + 64] = b1.z; Bs[lkq + 3][lrow + 64] = b1.w;
        __syncthreads();

        #pragma unroll
        for (int kk = 0; kk < BK; kk++) {
            float ra[TM], rb[TN];
            *(float4*)(ra)     = *(const float4*)&As[kk][ty * TM];
            *(float4*)(ra + 4) = *(const float4*)&As[kk][ty * TM + 4];
            *(float4*)(rb)     = *(const float4*)&Bs[kk][tx * TN];
            *(float4*)(rb + 4) = *(const float4*)&Bs[kk][tx * TN + 4];
            #pragma unroll
            for (int i = 0; i < TM; i++)
                #pragma unroll
                for (int j = 0; j < TN; j++)
                    acc[i][j] = fmaf(ra[i], rb[j], acc[i][j]);
        }
        __syncthreads();
    }

    // epilogue
    #pragma unroll
    for (int i = 0; i < TM; i++) {
        int m = m0 + ty * TM + i;
        if (m >= cnt) continue;
        #pragma unroll
        for (int j = 0; j < TN; j++) {
            int c = n0 + tx * TN + j;
            float v = acc[i][j] + bias[e * N + c];
            if (PHASE == 1) {
                v = 0.5f * v * (1.f + erff(v * 0.70710678118654752f));  // exact GELU
                g_H[((size_t)e * NTOK + m) * N + c] = v;
            } else {
                g_Z[((size_t)e * NTOK + m) * N + c] = v;
            }
        }
    }
}

// ---------------- combine: residual + LayerNorm + weighted sum --------------
__global__ void combine_kernel(const float* __restrict__ x,
                               const float* __restrict__ gamma,
                               const float* __restrict__ beta,
                               float* __restrict__ out) {
    const int t   = blockIdx.x;
    const int tid = threadIdx.x;    // 256, each owns 4 contiguous elements
    __shared__ float ssum[8], ssq[8];

    const float4 xv = *(const float4*)(x + (size_t)t * DM + tid * 4);
    float acc[4] = {0.f, 0.f, 0.f, 0.f};

    #pragma unroll
    for (int p = 0; p < 2; p++) {
        int   e   = g_eid [t * 2 + p];
        int   s   = g_slot[t * 2 + p];
        float wgt = g_wt  [t * 2 + p];

        const float4 zv = *(const float4*)(g_Z + ((size_t)e * NTOK + s) * DM + tid * 4);
        float z[4] = {xv.x + zv.x, xv.y + zv.y, xv.z + zv.z, xv.w + zv.w};

        float sum = 0.f, sq = 0.f;
        #pragma unroll
        for (int i = 0; i < 4; i++) { sum += z[i]; sq += z[i] * z[i]; }
        #pragma unroll
        for (int o = 16; o; o >>= 1) {
            sum += __shfl_xor_sync(0xffffffffu, sum, o);
            sq  += __shfl_xor_sync(0xffffffffu, sq,  o);
        }
        int w = tid >> 5, lane = tid & 31;
        if (lane == 0) { ssum[w] = sum; ssq[w] = sq; }
        __syncthreads();
        float tsum = 0.f, tsq = 0.f;
        #pragma unroll
        for (int i = 0; i < 8; i++) { tsum += ssum[i]; tsq += ssq[i]; }
        __syncthreads();

        float mu   = tsum * (1.f / DM);
        float var  = tsq * (1.f / DM) - mu * mu;
        float rstd = rsqrtf(var + 1e-6f);

        const float4 gv = *(const float4*)(gamma + (size_t)e * DM + tid * 4);
        const float4 bv = *(const float4*)(beta  + (size_t)e * DM + tid * 4);
        const float g4[4] = {gv.x, gv.y, gv.z, gv.w};
        const float b4[4] = {bv.x, bv.y, bv.z, bv.w};
        #pragma unroll
        for (int i = 0; i < 4; i++)
            acc[i] += wgt * ((z[i] - mu) * rstd * g4[i] + b4[i]);
    }

    float4 o4 = {acc[0], acc[1], acc[2], acc[3]};
    *(float4*)(out + (size_t)t * DM + tid * 4) = o4;
}

// ---------------- launch -----------------------------------------------------
extern "C" void kernel_launch(void* const* d_in, const int* in_sizes, int n_in,
                              void* d_out, int out_size) {
    const float* x     = (const float*)d_in[0];
    const float* gw    = (const float*)d_in[1];
    const float* w1    = (const float*)d_in[2];
    const float* b1    = (const float*)d_in[3];
    const float* w2    = (const float*)d_in[4];
    const float* b2    = (const float*)d_in[5];
    const float* gamma = (const float*)d_in[6];
    const float* beta  = (const float*)d_in[7];
    float* out = (float*)d_out;

    reset_kernel<<<1, 32>>>();
    gate_kernel<<<NTOK, 128>>>(x, gw);

    dim3 g1(DH / 128, NTOK / 128, NE);
    gemm_kernel<1><<<g1, 256>>>(x, w1, b1);

    dim3 g2(DM / 128, NTOK / 128, NE);
    gemm_kernel<2><<<g2, 256>>>(nullptr, w2, b2);

    combine_kernel<<<NTOK, 256>>>(x, gamma, beta, out);
}

// round 7
// speedup vs baseline: 2.2530x; 2.2530x over previous
#include <cuda_runtime.h>
#include <cuda_bf16.h>
#include <math.h>
#include <stdint.h>

#define NTOK 16384
#define DM   1024
#define NE   4
#define DH   2048

// ------------------------- device scratch ------------------------------------
__device__ int   g_count[NE];
__device__ int   g_tok [NE * NTOK];
__device__ int   g_eid [NTOK * 2];
__device__ int   g_slot[NTOK * 2];
__device__ float g_wt  [NTOK * 2];

__device__ __nv_bfloat16 g_xh [(size_t)NTOK * DM];
__device__ __nv_bfloat16 g_xl [(size_t)NTOK * DM];
__device__ __nv_bfloat16 g_w1h[(size_t)NE * DH * DM];
__device__ __nv_bfloat16 g_w1l[(size_t)NE * DH * DM];
__device__ __nv_bfloat16 g_w2h[(size_t)NE * DM * DH];
__device__ __nv_bfloat16 g_w2l[(size_t)NE * DM * DH];
__device__ __nv_bfloat16 g_Hh [(size_t)NE * NTOK * DH];
__device__ __nv_bfloat16 g_Hl [(size_t)NE * NTOK * DH];
__device__ float         g_Z  [(size_t)NE * NTOK * DM];

// ------------------------- PTX helpers (no 'a' features!) ---------------------
__device__ __forceinline__ uint32_t smem_u32(const void* p) {
    uint32_t a;
    asm("{ .reg .u64 t; cvta.to.shared.u64 t, %1; cvt.u32.u64 %0, t; }" : "=r"(a) : "l"(p));
    return a;
}
__device__ __forceinline__ void cpa16(uint32_t dst, const void* src) {
    asm volatile("cp.async.cg.shared.global [%0], [%1], 16;" :: "r"(dst), "l"(src));
}
__device__ __forceinline__ void cpa_commit() {
    asm volatile("cp.async.commit_group;" ::: "memory");
}
template <int N> __device__ __forceinline__ void cpa_wait() {
    asm volatile("cp.async.wait_group %0;" :: "n"(N) : "memory");
}
__device__ __forceinline__ void ldsm4(uint32_t* r, uint32_t addr) {
    asm volatile("ldmatrix.sync.aligned.m8n8.x4.shared.b16 {%0,%1,%2,%3}, [%4];"
                 : "=r"(r[0]), "=r"(r[1]), "=r"(r[2]), "=r"(r[3]) : "r"(addr));
}
__device__ __forceinline__ void mma_bf16(float* c, const uint32_t* a,
                                         uint32_t b0, uint32_t b1) {
    asm volatile(
        "mma.sync.aligned.m16n8k16.row.col.f32.bf16.bf16.f32 "
        "{%0,%1,%2,%3}, {%4,%5,%6,%7}, {%8,%9}, {%0,%1,%2,%3};"
        : "+f"(c[0]), "+f"(c[1]), "+f"(c[2]), "+f"(c[3])
        : "r"(a[0]), "r"(a[1]), "r"(a[2]), "r"(a[3]), "r"(b0), "r"(b1));
}

// ------------------------- small kernels -------------------------------------
__global__ void reset_kernel() {
    if (threadIdx.x < NE) g_count[threadIdx.x] = 0;
}

__global__ void gate_kernel(const float* __restrict__ x,
                            const float* __restrict__ gw) {
    int t = blockIdx.x, tid = threadIdx.x, w = tid >> 5, lane = tid & 31;
    const float4* xr = (const float4*)(x + (size_t)t * DM);
    const float4* gr = (const float4*)(gw + (size_t)w * DM);
    float s = 0.f;
    for (int k = lane; k < DM / 4; k += 32) {
        float4 a = xr[k], b = gr[k];
        s += a.x * b.x + a.y * b.y + a.z * b.z + a.w * b.w;
    }
    #pragma unroll
    for (int o = 16; o; o >>= 1) s += __shfl_xor_sync(0xffffffffu, s, o);
    __shared__ float sc[NE];
    if (lane == 0) sc[w] = s;
    __syncthreads();
    if (tid == 0) {
        int i0 = 0;
        #pragma unroll
        for (int i = 1; i < NE; i++) if (sc[i] > sc[i0]) i0 = i;
        int i1 = -1;
        #pragma unroll
        for (int i = 0; i < NE; i++) {
            if (i == i0) continue;
            if (i1 < 0 || sc[i] > sc[i1]) i1 = i;
        }
        float m = fmaxf(sc[i0], sc[i1]);
        float e0 = expf(sc[i0] - m), e1 = expf(sc[i1] - m);
        float inv = 1.f / (e0 + e1);
        int s0 = atomicAdd(&g_count[i0], 1);
        int s1 = atomicAdd(&g_count[i1], 1);
        g_eid [t * 2] = i0;  g_eid [t * 2 + 1] = i1;
        g_slot[t * 2] = s0;  g_slot[t * 2 + 1] = s1;
        g_wt  [t * 2] = e0 * inv;
        g_wt  [t * 2 + 1] = e1 * inv;
        g_tok[i0 * NTOK + s0] = t;
        g_tok[i1 * NTOK + s1] = t;
    }
}

// fp32 -> bf16 hi/lo split
__global__ void split_kernel(const float* __restrict__ src,
                             __nv_bfloat16* __restrict__ hi,
                             __nv_bfloat16* __restrict__ lo, int n4) {
    int i = blockIdx.x * blockDim.x + threadIdx.x;
    if (i >= n4) return;
    float4 v = ((const float4*)src)[i];
    __nv_bfloat16 h[4], l[4];
    float vv[4] = {v.x, v.y, v.z, v.w};
    #pragma unroll
    for (int j = 0; j < 4; j++) {
        h[j] = __float2bfloat16_rn(vv[j]);
        l[j] = __float2bfloat16_rn(vv[j] - __bfloat162float(h[j]));
    }
    ((uint2*)hi)[i] = *(uint2*)h;
    ((uint2*)lo)[i] = *(uint2*)l;
}

// ------------------------- HMMA GEMM ------------------------------------------
// C[m,n] = sum_k A[m,k]*B[n,k]; bf16 hi/lo split: AhBh + AlBh + AhBl.
// CTA tile 128x256, BK=32, 8 warps (2m x 4n), warp tile 64x64, 3-stage cp.async.
#define BM 128
#define BN 256
#define BK 32
#define ROWB 80            // padded row: 32 bf16 (64B) + 16B pad
#define OFF_AH 0
#define OFF_AL (BM * ROWB)                // 10240
#define OFF_BH (2 * BM * ROWB)            // 20480
#define OFF_BL (2 * BM * ROWB + BN * ROWB)// 40960
#define STG    (2 * BM * ROWB + 2 * BN * ROWB)  // 61440
#define SMEM_TOTAL (3 * STG)              // 184320

template <int PHASE>
__global__ void __launch_bounds__(256, 1)
gemm_mma(const float* __restrict__ bias) {
    constexpr int K = (PHASE == 1) ? DM : DH;
    constexpr int N = (PHASE == 1) ? DH : DM;
    constexpr int S = K / BK;

    const int e   = blockIdx.z;
    const int cnt = g_count[e];
    const int m0  = blockIdx.y * BM;
    if (m0 >= cnt) return;
    const int n0  = blockIdx.x * BN;

    extern __shared__ char dsm[];
    const uint32_t BUF = smem_u32(dsm);

    const int tid  = threadIdx.x;
    const int lane = tid & 31;
    const int wid  = tid >> 5;
    const int wm   = wid >> 2;            // 0..1
    const int wn   = wid & 3;             // 0..3

    // -------- global row pointers for cp.async --------
    const __nv_bfloat16 *aph[2], *apl[2];
    #pragma unroll
    for (int p = 0; p < 2; p++) {
        int r = (tid >> 2) + p * 64;      // 0..127
        if (PHASE == 1) {
            int row = m0 + r;
            int tok = (row < cnt) ? g_tok[e * NTOK + row] : 0;
            aph[p] = g_xh + (size_t)tok * DM;
            apl[p] = g_xl + (size_t)tok * DM;
        } else {
            size_t rr = (size_t)e * NTOK + m0 + r;
            aph[p] = g_Hh + rr * DH;
            apl[p] = g_Hl + rr * DH;
        }
    }
    const __nv_bfloat16* Wh = (PHASE == 1) ? g_w1h : g_w2h;
    const __nv_bfloat16* Wl = (PHASE == 1) ? g_w1l : g_w2l;
    const __nv_bfloat16 *bph[4], *bpl[4];
    #pragma unroll
    for (int p = 0; p < 4; p++) {
        int r = (tid >> 2) + p * 64;      // 0..255
        bph[p] = Wh + ((size_t)e * N + n0 + r) * K;
        bpl[p] = Wl + ((size_t)e * N + n0 + r) * K;
    }

    const int  seg  = (tid & 3) * 8;      // element offset in row
    const uint32_t soff = (uint32_t)((tid & 3) * 16);

    auto load_stage = [&](int s) {
        const int kb = s * BK;
        const uint32_t sb = BUF + (uint32_t)(s % 3) * STG;
        #pragma unroll
        for (int p = 0; p < 2; p++) {
            int r = (tid >> 2) + p * 64;
            uint32_t so = sb + (uint32_t)r * ROWB + soff;
            cpa16(so + OFF_AH, aph[p] + kb + seg);
            cpa16(so + OFF_AL, apl[p] + kb + seg);
        }
        #pragma unroll
        for (int p = 0; p < 4; p++) {
            int r = (tid >> 2) + p * 64;
            uint32_t so = sb + (uint32_t)r * ROWB + soff;
            cpa16(so + OFF_BH, bph[p] + kb + seg);
            cpa16(so + OFF_BL, bpl[p] + kb + seg);
        }
        cpa_commit();
    };

    // ldmatrix per-lane offset: mat = lane>>3 selects (row8, col16B) quadrant
    const int mat = lane >> 3;
    const uint32_t lds_off =
        (uint32_t)(((mat & 1) * 8 + (lane & 7)) * ROWB + (mat >> 1) * 16);

    float acc[4][8][4];
    #pragma unroll
    for (int i = 0; i < 4; i++)
        #pragma unroll
        for (int j = 0; j < 8; j++)
            #pragma unroll
            for (int q = 0; q < 4; q++) acc[i][j][q] = 0.f;

    load_stage(0);
    load_stage(1);

    for (int s = 0; s < S; s++) {
        if (s == S - 1) cpa_wait<0>(); else cpa_wait<1>();
        __syncthreads();
        if (s + 2 < S) load_stage(s + 2);

        const uint32_t sb = BUF + (uint32_t)(s % 3) * STG;
        #pragma unroll
        for (int kk = 0; kk < 2; kk++) {
            const uint32_t kb = (uint32_t)(kk * 32) + lds_off;
            uint32_t ah[4][4], al[4][4], bb[4][4];
            #pragma unroll
            for (int mt = 0; mt < 4; mt++) {
                uint32_t ro = (uint32_t)((wm * 64 + mt * 16) * ROWB) + kb;
                ldsm4(ah[mt], sb + OFF_AH + ro);
                ldsm4(al[mt], sb + OFF_AL + ro);
            }
            #pragma unroll
            for (int nb = 0; nb < 4; nb++)
                ldsm4(bb[nb], sb + OFF_BH + (uint32_t)((wn * 64 + nb * 16) * ROWB) + kb);
            #pragma unroll
            for (int mt = 0; mt < 4; mt++)
                #pragma unroll
                for (int nb = 0; nb < 4; nb++) {
                    mma_bf16(acc[mt][2 * nb],     ah[mt], bb[nb][0], bb[nb][2]);
                    mma_bf16(acc[mt][2 * nb + 1], ah[mt], bb[nb][1], bb[nb][3]);
                }
            #pragma unroll
            for (int mt = 0; mt < 4; mt++)
                #pragma unroll
                for (int nb = 0; nb < 4; nb++) {
                    mma_bf16(acc[mt][2 * nb],     al[mt], bb[nb][0], bb[nb][2]);
                    mma_bf16(acc[mt][2 * nb + 1], al[mt], bb[nb][1], bb[nb][3]);
                }
            #pragma unroll
            for (int nb = 0; nb < 4; nb++)
                ldsm4(bb[nb], sb + OFF_BL + (uint32_t)((wn * 64 + nb * 16) * ROWB) + kb);
            #pragma unroll
            for (int mt = 0; mt < 4; mt++)
                #pragma unroll
                for (int nb = 0; nb < 4; nb++) {
                    mma_bf16(acc[mt][2 * nb],     ah[mt], bb[nb][0], bb[nb][2]);
                    mma_bf16(acc[mt][2 * nb + 1], ah[mt], bb[nb][1], bb[nb][3]);
                }
        }
    }

    // -------- epilogue --------
    const int grp = lane >> 2, qid = lane & 3;
    float bc[8][2];
    #pragma unroll
    for (int nt = 0; nt < 8; nt++) {
        int col = n0 + wn * 64 + nt * 8 + qid * 2;
        bc[nt][0] = __ldg(bias + e * N + col);
        bc[nt][1] = __ldg(bias + e * N + col + 1);
    }
    #pragma unroll
    for (int mt = 0; mt < 4; mt++) {
        #pragma unroll
        for (int h = 0; h < 2; h++) {
            int r = m0 + wm * 64 + mt * 16 + grp + h * 8;
            if (r >= cnt) continue;
            #pragma unroll
            for (int nt = 0; nt < 8; nt++) {
                int col = n0 + wn * 64 + nt * 8 + qid * 2;
                float v0 = acc[mt][nt][h * 2 + 0] + bc[nt][0];
                float v1 = acc[mt][nt][h * 2 + 1] + bc[nt][1];
                if (PHASE == 1) {
                    v0 = 0.5f * v0 * (1.f + erff(v0 * 0.70710678118654752f));
                    v1 = 0.5f * v1 * (1.f + erff(v1 * 0.70710678118654752f));
                    __nv_bfloat162 hv, lv;
                    hv.x = __float2bfloat16_rn(v0);
                    hv.y = __float2bfloat16_rn(v1);
                    lv.x = __float2bfloat16_rn(v0 - __bfloat162float(hv.x));
                    lv.y = __float2bfloat16_rn(v1 - __bfloat162float(hv.y));
                    size_t off = ((size_t)e * NTOK + r) * DH + col;
                    *(__nv_bfloat162*)(g_Hh + off) = hv;
                    *(__nv_bfloat162*)(g_Hl + off) = lv;
                } else {
                    float2 o = {v0, v1};
                    *(float2*)(g_Z + ((size_t)e * NTOK + r) * DM + col) = o;
                }
            }
        }
    }
}

// ------------------------- combine -------------------------------------------
__global__ void combine_kernel(const float* __restrict__ x,
                               const float* __restrict__ gamma,
                               const float* __restrict__ beta,
                               float* __restrict__ out) {
    const int t = blockIdx.x, tid = threadIdx.x;
    __shared__ float ssum[8], ssq[8];
    const float4 xv = *(const float4*)(x + (size_t)t * DM + tid * 4);
    float acc[4] = {0.f, 0.f, 0.f, 0.f};
    #pragma unroll
    for (int p = 0; p < 2; p++) {
        int e = g_eid[t * 2 + p], s = g_slot[t * 2 + p];
        float wgt = g_wt[t * 2 + p];
        const float4 zv = *(const float4*)(g_Z + ((size_t)e * NTOK + s) * DM + tid * 4);
        float z[4] = {xv.x + zv.x, xv.y + zv.y, xv.z + zv.z, xv.w + zv.w};
        float sum = 0.f, sq = 0.f;
        #pragma unroll
        for (int i = 0; i < 4; i++) { sum += z[i]; sq += z[i] * z[i]; }
        #pragma unroll
        for (int o = 16; o; o >>= 1) {
            sum += __shfl_xor_sync(0xffffffffu, sum, o);
            sq  += __shfl_xor_sync(0xffffffffu, sq,  o);
        }
        int w = tid >> 5, lane = tid & 31;
        if (lane == 0) { ssum[w] = sum; ssq[w] = sq; }
        __syncthreads();
        float tsum = 0.f, tsq = 0.f;
        #pragma unroll
        for (int i = 0; i < 8; i++) { tsum += ssum[i]; tsq += ssq[i]; }
        __syncthreads();
        float mu = tsum * (1.f / DM);
        float var = tsq * (1.f / DM) - mu * mu;
        float rstd = rsqrtf(var + 1e-6f);
        const float4 gv = *(const float4*)(gamma + (size_t)e * DM + tid * 4);
        const float4 bv = *(const float4*)(beta  + (size_t)e * DM + tid * 4);
        const float g4[4] = {gv.x, gv.y, gv.z, gv.w};
        const float b4[4] = {bv.x, bv.y, bv.z, bv.w};
        #pragma unroll
        for (int i = 0; i < 4; i++)
            acc[i] += wgt * ((z[i] - mu) * rstd * g4[i] + b4[i]);
    }
    float4 o4 = {acc[0], acc[1], acc[2], acc[3]};
    *(float4*)(out + (size_t)t * DM + tid * 4) = o4;
}

// ------------------------- launch --------------------------------------------
extern "C" void kernel_launch(void* const* d_in, const int* in_sizes, int n_in,
                              void* d_out, int out_size) {
    const float* x     = (const float*)d_in[0];
    const float* gw    = (const float*)d_in[1];
    const float* w1    = (const float*)d_in[2];
    const float* b1    = (const float*)d_in[3];
    const float* w2    = (const float*)d_in[4];
    const float* b2    = (const float*)d_in[5];
    const float* gamma = (const float*)d_in[6];
    const float* beta  = (const float*)d_in[7];
    float* out = (float*)d_out;

    cudaFuncSetAttribute(gemm_mma<1>, cudaFuncAttributeMaxDynamicSharedMemorySize, SMEM_TOTAL);
    cudaFuncSetAttribute(gemm_mma<2>, cudaFuncAttributeMaxDynamicSharedMemorySize, SMEM_TOTAL);

    void *pxh, *pxl, *pw1h, *pw1l, *pw2h, *pw2l;
    cudaGetSymbolAddress(&pxh,  g_xh);
    cudaGetSymbolAddress(&pxl,  g_xl);
    cudaGetSymbolAddress(&pw1h, g_w1h);
    cudaGetSymbolAddress(&pw1l, g_w1l);
    cudaGetSymbolAddress(&pw2h, g_w2h);
    cudaGetSymbolAddress(&pw2l, g_w2l);

    reset_kernel<<<1, 32>>>();
    gate_kernel<<<NTOK, 128>>>(x, gw);

    {
        int n4 = NTOK * DM / 4;
        split_kernel<<<(n4 + 255) / 256, 256>>>(x, (__nv_bfloat16*)pxh, (__nv_bfloat16*)pxl, n4);
    }
    {
        int n4 = NE * DH * DM / 4;
        split_kernel<<<(n4 + 255) / 256, 256>>>(w1, (__nv_bfloat16*)pw1h, (__nv_bfloat16*)pw1l, n4);
        split_kernel<<<(n4 + 255) / 256, 256>>>(w2, (__nv_bfloat16*)pw2h, (__nv_bfloat16*)pw2l, n4);
    }

    dim3 g1(DH / BN, NTOK / BM, NE);
    gemm_mma<1><<<g1, 256, SMEM_TOTAL>>>(b1);

    dim3 g2(DM / BN, NTOK / BM, NE);
    gemm_mma<2><<<g2, 256, SMEM_TOTAL>>>(b2);

    combine_kernel<<<NTOK, 256>>>(x, gamma, beta, out);
}